// round 12
// baseline (speedup 1.0000x reference)
#include <cuda_runtime.h>

// QuadratureFunction: per-cell DOF gather (3 vertex + 3x2 edge w/ orientation
// flip + 1 face) contracted against y[C, NB=10, Q=16] -> out[C, Q=16].
//
// HBM-streaming bound: steady-state DRAM traffic is y (320MB) + out (32MB)
// per graph replay; indices + dof arrays (27MB) stay L2-resident across
// replays (validated R4 vs R6). Mapping: 4 threads/cell, 4 q-points each.
//
// R12: persistent grid (4 blocks/SM x 152 SMs = 608 blocks) + grid-stride
// loop to remove the 0.43-wave tail of the flat 3907-block launch (~5%).
// R5's version of this regressed because the loop's +2 regs (34) silently
// dropped residency to 3 blocks/SM; this time __launch_bounds__(512, 4)
// PINS 4-blocks/SM residency (forces regs <= 32).
//
// Cache policy: __ldcs only on y (one-shot 320MB stream, keep L2 clean),
// __stcs on out; everything else default-cached for cross-replay residency.

#define NB 10
#define Q  16

__global__ __launch_bounds__(512, 4)
void quad_kernel(const float* __restrict__ vertex_dofs,
                 const float* __restrict__ edge_dofs,
                 const float* __restrict__ face_dofs,
                 const float* __restrict__ y,
                 const int*   __restrict__ faces,
                 const int*   __restrict__ faces_to_edges,
                 const int*   __restrict__ edge_orientation,
                 float*       __restrict__ out,
                 int C)
{
    const int total = C * 4;                     // one item = (cell, 4 q-pts)
    const int span  = gridDim.x * blockDim.x;

    for (int t = blockIdx.x * blockDim.x + threadIdx.x; t < total; t += span) {
        int c  = t >> 2;            // cell index (4 threads per cell)
        int q0 = (t & 3) << 2;      // starting quadrature point (0,4,8,12)

        // --- issue all 10 streaming y loads up front (max MLP) ---
        const float4* yb = reinterpret_cast<const float4*>(
            y + (size_t)c * (NB * Q) + q0);

        float4 yv[NB];
        #pragma unroll
        for (int b = 0; b < NB; b++)
            yv[b] = __ldcs(&yb[b * (Q / 4)]);   // evict-first

        // --- gather local dofs (default-cached: L2-persistent across graph
        //     replays). Duplicate addresses within the 4 lanes of a cell
        //     coalesce to a single transaction. ---
        float dofs[NB];

        int v0 = faces[3 * c + 0];
        int v1 = faces[3 * c + 1];
        int v2 = faces[3 * c + 2];
        dofs[0] = vertex_dofs[v0];   // DV = 1
        dofs[1] = vertex_dofs[v1];
        dofs[2] = vertex_dofs[v2];

        #pragma unroll
        for (int e = 0; e < 3; e++) {
            int ei = faces_to_edges[3 * c + e];
            int o  = edge_orientation[3 * c + e];
            // DE = 2: keep order when o==1, flip when o==0
            float d0 = edge_dofs[2 * ei + 0];
            float d1 = edge_dofs[2 * ei + 1];
            dofs[3 + 2 * e + 0] = o ? d0 : d1;
            dofs[3 + 2 * e + 1] = o ? d1 : d0;
        }

        dofs[9] = face_dofs[c];      // DF = 1

        // --- contraction: out[c, q0..q0+3] = sum_b dofs[b]*y[c,b,q0..q0+3] ---
        float4 acc = make_float4(0.f, 0.f, 0.f, 0.f);
        #pragma unroll
        for (int b = 0; b < NB; b++) {
            acc.x = fmaf(dofs[b], yv[b].x, acc.x);
            acc.y = fmaf(dofs[b], yv[b].y, acc.y);
            acc.z = fmaf(dofs[b], yv[b].z, acc.z);
            acc.w = fmaf(dofs[b], yv[b].w, acc.w);
        }

        __stcs(reinterpret_cast<float4*>(out + (size_t)c * Q + q0), acc);
    }
}

extern "C" void kernel_launch(void* const* d_in, const int* in_sizes, int n_in,
                              void* d_out, int out_size)
{
    const float* vertex_dofs      = (const float*)d_in[0];
    const float* edge_dofs        = (const float*)d_in[1];
    const float* face_dofs        = (const float*)d_in[2];
    const float* y                = (const float*)d_in[3];
    const int*   faces            = (const int*)d_in[4];
    const int*   faces_to_edges   = (const int*)d_in[5];
    const int*   edge_orientation = (const int*)d_in[6];
    float*       out              = (float*)d_out;

    int C = in_sizes[2];               // face_dofs has C*DF = C elements

    // Persistent grid: 4 blocks/SM (residency pinned by launch_bounds)
    // x 152 SMs (GB300). Cap at flat-launch size for small C.
    int block = 512;
    int grid  = 4 * 152;
    int total_threads = C * 4;
    int max_grid = (total_threads + block - 1) / block;
    if (grid > max_grid) grid = max_grid;

    quad_kernel<<<grid, block>>>(vertex_dofs, edge_dofs, face_dofs, y,
                                 faces, faces_to_edges, edge_orientation,
                                 out, C);
}

// round 13
// speedup vs baseline: 1.0756x; 1.0756x over previous
#include <cuda_runtime.h>

// QuadratureFunction: per-cell DOF gather (3 vertex + 3x2 edge w/ orientation
// flip + 1 face) contracted against y[C, NB=10, Q=16] -> out[C, Q=16].
//
// Steady-state DRAM traffic per graph replay: y (320MB, __ldcs) + out (32MB,
// __stcs). Indices + dof arrays (27MB) L2-resident across replays (R4 vs R6).
// Flat launch (persistent grid regressed in R12: per-warp iteration
// serialization sagged outstanding-load depth, DRAM% 79.5 -> 74.2).
//
// R13: MLP boost. At __launch_bounds__(512,4) the kernel was squeezed to 32
// regs -> ptxas could not keep 10 outstanding float4 y-loads (40 dest regs)
// in flight; MLP_eff ~6 capped DRAM at ~79%. Switch to block=256 with
// __launch_bounds__(256, 6): 1536 thr/SM (48 warps, occ 75%) but 42
// regs/thread -> near-full front-batching of the 10-load burst.
// Outstanding loads/SM rises ~19%.

#define NB 10
#define Q  16

__global__ __launch_bounds__(256, 6)
void quad_kernel(const float* __restrict__ vertex_dofs,
                 const float* __restrict__ edge_dofs,
                 const float* __restrict__ face_dofs,
                 const float* __restrict__ y,
                 const int*   __restrict__ faces,
                 const int*   __restrict__ faces_to_edges,
                 const int*   __restrict__ edge_orientation,
                 float*       __restrict__ out,
                 int C)
{
    int t = blockIdx.x * blockDim.x + threadIdx.x;
    int c  = t >> 2;            // cell index (4 threads per cell)
    int q0 = (t & 3) << 2;      // starting quadrature point (0,4,8,12)
    if (c >= C) return;

    // --- issue all 10 streaming y loads up front (max MLP; regs available) ---
    const float4* yb = reinterpret_cast<const float4*>(
        y + (size_t)c * (NB * Q) + q0);

    float4 yv[NB];
    #pragma unroll
    for (int b = 0; b < NB; b++)
        yv[b] = __ldcs(&yb[b * (Q / 4)]);   // evict-first: no L2 pollution

    // --- gather local dofs (default-cached: L2-persistent across graph
    //     replays). Duplicate addresses within the 4 lanes of a cell
    //     coalesce to a single transaction. ---
    float dofs[NB];

    int v0 = faces[3 * c + 0];
    int v1 = faces[3 * c + 1];
    int v2 = faces[3 * c + 2];
    dofs[0] = vertex_dofs[v0];   // DV = 1
    dofs[1] = vertex_dofs[v1];
    dofs[2] = vertex_dofs[v2];

    #pragma unroll
    for (int e = 0; e < 3; e++) {
        int ei = faces_to_edges[3 * c + e];
        int o  = edge_orientation[3 * c + e];
        // DE = 2: keep order when o==1, flip when o==0
        float d0 = edge_dofs[2 * ei + 0];
        float d1 = edge_dofs[2 * ei + 1];
        dofs[3 + 2 * e + 0] = o ? d0 : d1;
        dofs[3 + 2 * e + 1] = o ? d1 : d0;
    }

    dofs[9] = face_dofs[c];      // DF = 1

    // --- contraction: out[c, q0..q0+3] = sum_b dofs[b] * y[c, b, q0..q0+3] ---
    float4 acc = make_float4(0.f, 0.f, 0.f, 0.f);
    #pragma unroll
    for (int b = 0; b < NB; b++) {
        acc.x = fmaf(dofs[b], yv[b].x, acc.x);
        acc.y = fmaf(dofs[b], yv[b].y, acc.y);
        acc.z = fmaf(dofs[b], yv[b].z, acc.z);
        acc.w = fmaf(dofs[b], yv[b].w, acc.w);
    }

    __stcs(reinterpret_cast<float4*>(out + (size_t)c * Q + q0), acc);
}

extern "C" void kernel_launch(void* const* d_in, const int* in_sizes, int n_in,
                              void* d_out, int out_size)
{
    const float* vertex_dofs      = (const float*)d_in[0];
    const float* edge_dofs        = (const float*)d_in[1];
    const float* face_dofs        = (const float*)d_in[2];
    const float* y                = (const float*)d_in[3];
    const int*   faces            = (const int*)d_in[4];
    const int*   faces_to_edges   = (const int*)d_in[5];
    const int*   edge_orientation = (const int*)d_in[6];
    float*       out              = (float*)d_out;

    int C = in_sizes[2];               // face_dofs has C*DF = C elements
    int total_threads = C * 4;         // 4 threads per cell
    int block = 256;
    int grid = (total_threads + block - 1) / block;

    quad_kernel<<<grid, block>>>(vertex_dofs, edge_dofs, face_dofs, y,
                                 faces, faces_to_edges, edge_orientation,
                                 out, C);
}